// round 5
// baseline (speedup 1.0000x reference)
#include <cuda_runtime.h>

#define BATCH 2048
#define ISIZE 2048
#define OSIZE 2048
#define NIN   6
#define KTAB  64

typedef unsigned long long ull;

// Static scratch: transposed x, xT[m][b]  (16 MB)
__device__ float g_xT[(size_t)ISIZE * BATCH];

__device__ __forceinline__ ull pack2(float lo, float hi) {
    ull r;
    asm("mov.b64 %0, {%1, %2};" : "=l"(r) : "f"(lo), "f"(hi));
    return r;
}
__device__ __forceinline__ ull fma2(ull a, ull b, ull c) {
    ull r;
    asm("fma.rn.f32x2 %0, %1, %2, %3;" : "=l"(r) : "l"(a), "l"(b), "l"(c));
    return r;
}
__device__ __forceinline__ ull mul2(ull a, ull b) {
    ull r;
    asm("mul.rn.f32x2 %0, %1, %2;" : "=l"(r) : "l"(a), "l"(b));
    return r;
}
__device__ __forceinline__ float2 unpack2(ull v) {
    float2 f;
    asm("mov.b64 {%0, %1}, %2;" : "=f"(f.x), "=f"(f.y) : "l"(v));
    return f;
}

// ---------------------------------------------------------------------------
// Kernel 1: transpose x [BATCH][ISIZE] -> g_xT [ISIZE][BATCH]
// ---------------------------------------------------------------------------
__global__ void transpose_kernel(const float* __restrict__ x) {
    __shared__ float tile[32][33];
    int bx = blockIdx.x * 32;   // input-feature base
    int by = blockIdx.y * 32;   // batch base
    int tx = threadIdx.x, ty = threadIdx.y;
#pragma unroll
    for (int j = 0; j < 32; j += 8)
        tile[ty + j][tx] = x[(size_t)(by + ty + j) * ISIZE + bx + tx];
    __syncthreads();
#pragma unroll
    for (int j = 0; j < 32; j += 8)
        g_xT[(size_t)(bx + ty + j) * BATCH + by + tx] = tile[tx][ty + j];
}

// ---------------------------------------------------------------------------
// Kernel 2: LUT evaluation.
//   CTA tile: 32 outputs x 256 batches (128 threads, 2 batches/thread, f32x2).
//   Levels 0-1 fused as bilinear quads with precomputed Mobius coefficients
//   (a, d0, d1, d01), broadcast-packed as ull in shared (LDS.128 loads).
//   Levels 2-5 are the standard lerp tree. 79 FFMA2-class ops per (o, b-pair).
//   Mapping dtype (int32 vs int64) detected per-CTA; offsets built in setup.
// ---------------------------------------------------------------------------
#define OT      32
#define THREADS 128
#define BT      (2 * THREADS)
#define NQ      (KTAB / 4)   // 16 quads

__global__ __launch_bounds__(THREADS)
void lut_kernel(const float* __restrict__ table,
                const void* __restrict__ mraw,
                float* __restrict__ out) {
    // quad coeffs, each duplicated into both f32x2 lanes:
    // s_q[o][q][0] = {(a,a),(d0,d0)}, s_q[o][q][1] = {(d1,d1),(d01,d01)}
    __shared__ __align__(16) ulonglong2 s_q[OT][NQ][2];
    __shared__ int s_off[OT][NIN];
    __shared__ int s_is64;

    const int tid   = threadIdx.x;
    const int obase = blockIdx.x * OT;
    const int bbase = blockIdx.y * BT;

    // Detect mapping dtype: int64 values < 2048 => odd 32-bit words are 0.
    const int* w32 = (const int*)mraw;
    if (tid == 0) {
        int z = 1;
#pragma unroll
        for (int i = 1; i < 16; i += 2) z &= (w32[i] == 0);
        s_is64 = z;
    }
    __syncthreads();
    const int is64 = s_is64;

    // Gather offsets.
    for (int p = tid; p < OT * NIN; p += THREADS) {
        int idx = (obase + p / NIN) * NIN + (p % NIN);
        int m = is64 ? (int)((const long long*)mraw)[idx] : w32[idx];
        s_off[p / NIN][p % NIN] = m * BATCH + bbase;
    }

    // Sigmoid + bilinear Mobius coefficients per quad of 4 table entries.
    // Entry k: bit0 = x0 state, bit1 = x1 state.
    for (int p = tid; p < OT * NQ; p += THREADS) {
        int o = p >> 4, q = p & (NQ - 1);
        const float* t = table + (size_t)(obase + o) * KTAB + 4 * q;
        float s0 = 1.0f / (1.0f + __expf(-t[0]));   // x0=0, x1=0
        float s1 = 1.0f / (1.0f + __expf(-t[1]));   // x0=1, x1=0
        float s2 = 1.0f / (1.0f + __expf(-t[2]));   // x0=0, x1=1
        float s3 = 1.0f / (1.0f + __expf(-t[3]));   // x0=1, x1=1
        float a   = s0;
        float d0  = s1 - s0;
        float d1  = s2 - s0;
        float d01 = s3 - s1 - s2 + s0;
        s_q[o][q][0] = make_ulonglong2(pack2(a, a), pack2(d0, d0));
        s_q[o][q][1] = make_ulonglong2(pack2(d1, d1), pack2(d01, d01));
    }
    __syncthreads();

    const ull NEG1 = pack2(-1.0f, -1.0f);
    const int bl = 2 * tid;

    float rlo[8], rhi[8];

    for (int og = 0; og < OT / 8; og++) {
#pragma unroll
        for (int oj = 0; oj < 8; oj++) {
            const int o = og * 8 + oj;

            // Gather 6 packed x-pairs (coalesced LDG.64 from transposed x).
            ull xv[NIN];
#pragma unroll
            for (int i = 0; i < NIN; i++)
                xv[i] = *(const ull*)(g_xT + s_off[o][i] + bl);

            const ull t01 = mul2(xv[0], xv[1]);

            // Levels 0-1 fused: 16 bilinear quads, 3 FFMA2 each.
            ull acc[NQ];
#pragma unroll
            for (int q = 0; q < NQ; q++) {
                ulonglong2 c0 = s_q[o][q][0];
                ulonglong2 c1 = s_q[o][q][1];
                ull r = fma2(xv[0], c0.y, c0.x);   // a + x0*d0
                r     = fma2(xv[1], c1.x, r);      //   + x1*d1
                acc[q] = fma2(t01, c1.y, r);       //   + x0x1*d01
            }

            // Levels 2-5: lerp tree over 16 values.
#pragma unroll
            for (int lvl = 2; lvl < 6; lvl++) {
                const int n = KTAB >> (lvl + 1);
#pragma unroll
                for (int k = 0; k < n; k++) {
                    ull d = fma2(acc[2 * k], NEG1, acc[2 * k + 1]);  // b - a
                    acc[k] = fma2(xv[lvl], d, acc[2 * k]);            // a + x*(b-a)
                }
            }

            float2 r = unpack2(acc[0]);
            rlo[oj] = r.x;
            rhi[oj] = r.y;
        }

        float4* p0 = (float4*)(out + (size_t)(bbase + bl) * OSIZE + obase + og * 8);
        float4* p1 = (float4*)(out + (size_t)(bbase + bl + 1) * OSIZE + obase + og * 8);
        p0[0] = make_float4(rlo[0], rlo[1], rlo[2], rlo[3]);
        p0[1] = make_float4(rlo[4], rlo[5], rlo[6], rlo[7]);
        p1[0] = make_float4(rhi[0], rhi[1], rhi[2], rhi[3]);
        p1[1] = make_float4(rhi[4], rhi[5], rhi[6], rhi[7]);
    }
}

// ---------------------------------------------------------------------------
extern "C" void kernel_launch(void* const* d_in, const int* in_sizes, int n_in,
                              void* d_out, int out_size) {
    const float* x     = (const float*)d_in[0];
    const float* table = (const float*)d_in[1];
    const void*  mraw  = d_in[2];
    float*       out   = (float*)d_out;

    (void)in_sizes; (void)n_in; (void)out_size;

    transpose_kernel<<<dim3(ISIZE / 32, BATCH / 32), dim3(32, 8)>>>(x);
    lut_kernel<<<dim3(OSIZE / OT, BATCH / BT), THREADS>>>(table, mraw, out);
}